// round 3
// baseline (speedup 1.0000x reference)
#include <cuda_runtime.h>
#include <cuda_bf16.h>
#include <cstdint>

// ---------------------------------------------------------------------------
// GAE: 4-layer GCN autoencoder. N=20000, IN=1024, HID=512, OUT=128, E=160000.
// out = [z (N,128) | h2 (N,128) | h4 (N,1024)] fp32.
// Uses A(XW^T) = (AX)W^T reordering so every scatter runs at the narrow width.
// ---------------------------------------------------------------------------

#define N_NODES 20000
#define IN_DIM  1024
#define HID_DIM 512
#define OUT_DIM 128
#define N_EDGES 160000

__device__ alignas(16) float g_T[(size_t)N_NODES * HID_DIM];  // scratch A (512 wide)
__device__ alignas(16) float g_H[(size_t)N_NODES * HID_DIM];  // scratch B (512 wide)
__device__ float g_deg[N_NODES];
__device__ float g_dinv[N_NODES];
__device__ float g_sn[N_NODES];
__device__ int   g_src[N_EDGES];
__device__ int   g_dst[N_EDGES];
__device__ float g_norm[N_EDGES];
__device__ int   g_is64;   // 1 if edge_index is int64, 0 if int32

// pointer selector: 0 = external, 1 = g_T, 2 = g_H
template <int SEL>
__device__ __forceinline__ float* pick(float* ext) {
    if (SEL == 1) return g_T;
    if (SEL == 2) return g_H;
    return ext;
}
template <int SEL>
__device__ __forceinline__ const float* pickc(const float* ext) {
    if (SEL == 1) return g_T;
    if (SEL == 2) return g_H;
    return ext;
}

// ---------------------------------------------------------------------------
// Edge-index dtype probe: int64 edge data with values < 2^31 has zero high
// words at every odd int32 position of row 0.
// ---------------------------------------------------------------------------
__global__ void k_probe_dtype(const int* __restrict__ ei32) {
    if (threadIdx.x == 0 && blockIdx.x == 0) {
        int z = (ei32[1] == 0) & (ei32[3] == 0) & (ei32[5] == 0) &
                (ei32[7] == 0) & (ei32[9] == 0) & (ei32[11] == 0);
        g_is64 = z;
    }
}

__device__ __forceinline__ int load_idx(const void* ei, int e_cnt, int row, int e) {
    if (g_is64) {
        long long v = ((const long long*)ei)[(size_t)row * e_cnt + e];
        return (int)v;
    }
    return ((const int*)ei)[(size_t)row * e_cnt + e];
}

// ---------------------------------------------------------------------------
// Degree / norm preprocessing
// ---------------------------------------------------------------------------
__global__ void k_deg_init(int n) {
    int i = blockIdx.x * blockDim.x + threadIdx.x;
    if (i < n) g_deg[i] = 1.0f;  // self loop
}

__global__ void k_deg_edges(const void* __restrict__ ei, int e_cnt, int n) {
    int e = blockIdx.x * blockDim.x + threadIdx.x;
    if (e < e_cnt) {
        int d = load_idx(ei, e_cnt, 1, e);
        if ((unsigned)d < (unsigned)n) atomicAdd(&g_deg[d], 1.0f);
    }
}

__global__ void k_dinv(int n) {
    int i = blockIdx.x * blockDim.x + threadIdx.x;
    if (i < n) {
        float r = rsqrtf(g_deg[i]);
        g_dinv[i] = r;
        g_sn[i] = r * r;
    }
}

__global__ void k_edge_prep(const void* __restrict__ ei, int e_cnt, int n) {
    int e = blockIdx.x * blockDim.x + threadIdx.x;
    if (e < e_cnt) {
        int s = load_idx(ei, e_cnt, 0, e);
        int d = load_idx(ei, e_cnt, 1, e);
        if ((unsigned)s >= (unsigned)n) s = 0;
        if ((unsigned)d >= (unsigned)n) d = 0;
        g_src[e] = s;
        g_dst[e] = d;
        g_norm[e] = g_dinv[s] * g_dinv[d];
    }
}

// ---------------------------------------------------------------------------
// SGEMM: C[M,Nn] = A[M,K] @ op(B) (+ bias[n] if bias != nullptr)
//   TB=1: B is [Nn,K] row-major (C = A@B^T);  TB=0: B is [K,Nn] row-major
//   ASEL / CSEL select internal scratch vs external pointer.
// K % 8 == 0, Nn % 128 == 0; M guarded.
// ---------------------------------------------------------------------------
#define BM 128
#define BN 128
#define BK 8
#define TM 8
#define TN 8

template <int TB, int ASEL, int CSEL>
__global__ __launch_bounds__(256)
void k_sgemm(int M, int Nn, int K,
             const float* __restrict__ Aext,
             const float* __restrict__ B,
             float* __restrict__ Cext,
             const float* __restrict__ bias) {
    const float* A = pickc<ASEL>(Aext);
    float*       C = pick<CSEL>(Cext);

    __shared__ float As[BK][BM];
    __shared__ float Bs[BK][BN];

    const int bx = blockIdx.x;
    const int by = blockIdx.y;
    const int tid = threadIdx.x;

    const int tcol = tid % (BN / TN);
    const int trow = tid / (BN / TN);

    float acc[TM][TN];
#pragma unroll
    for (int i = 0; i < TM; i++)
#pragma unroll
        for (int j = 0; j < TN; j++) acc[i][j] = 0.0f;

    const int aRow = tid >> 1;        // 0..127
    const int aCol = (tid & 1) << 2;  // 0 or 4

    for (int k0 = 0; k0 < K; k0 += BK) {
        {
            int m = by * BM + aRow;
            float4 av = make_float4(0.f, 0.f, 0.f, 0.f);
            if (m < M) av = *(const float4*)(A + (size_t)m * K + k0 + aCol);
            As[aCol + 0][aRow] = av.x;
            As[aCol + 1][aRow] = av.y;
            As[aCol + 2][aRow] = av.z;
            As[aCol + 3][aRow] = av.w;
        }
        if (TB) {
            int nn = bx * BN + aRow;
            float4 bv = *(const float4*)(B + (size_t)nn * K + k0 + aCol);
            Bs[aCol + 0][aRow] = bv.x;
            Bs[aCol + 1][aRow] = bv.y;
            Bs[aCol + 2][aRow] = bv.z;
            Bs[aCol + 3][aRow] = bv.w;
        } else {
            int kk = tid >> 5;
            int nn = (tid & 31) << 2;
            float4 bv = *(const float4*)(B + (size_t)(k0 + kk) * Nn + bx * BN + nn);
            *(float4*)&Bs[kk][nn] = bv;
        }
        __syncthreads();

#pragma unroll
        for (int k = 0; k < BK; k++) {
            float ra[TM], rb[TN];
#pragma unroll
            for (int i = 0; i < TM; i++) ra[i] = As[k][trow * TM + i];
#pragma unroll
            for (int j = 0; j < TN; j++) rb[j] = Bs[k][tcol * TN + j];
#pragma unroll
            for (int i = 0; i < TM; i++)
#pragma unroll
                for (int j = 0; j < TN; j++) acc[i][j] += ra[i] * rb[j];
        }
        __syncthreads();
    }

    float bv[TN];
#pragma unroll
    for (int j = 0; j < TN; j++)
        bv[j] = bias ? bias[bx * BN + tcol * TN + j] : 0.0f;

#pragma unroll
    for (int i = 0; i < TM; i++) {
        int m = by * BM + trow * TM + i;
        if (m < M) {
            float* cp = C + (size_t)m * Nn + bx * BN + tcol * TN;
            *(float4*)(cp + 0) = make_float4(acc[i][0] + bv[0], acc[i][1] + bv[1],
                                             acc[i][2] + bv[2], acc[i][3] + bv[3]);
            *(float4*)(cp + 4) = make_float4(acc[i][4] + bv[4], acc[i][5] + bv[5],
                                             acc[i][6] + bv[6], acc[i][7] + bv[7]);
        }
    }
}

// ---------------------------------------------------------------------------
// Self-loop init: DST[i,f] = (bias? b[f]:0) + SRC[i,f] * sn[i]
// ---------------------------------------------------------------------------
template <int SSEL, int DSEL>
__global__ void k_init_self(const float* __restrict__ Sext,
                            float* __restrict__ Dext,
                            const float* __restrict__ b,
                            int n, int logF) {
    const float* S = pickc<SSEL>(Sext);
    float*       D = pick<DSEL>(Dext);
    int idx = blockIdx.x * blockDim.x + threadIdx.x;
    int total = n << logF;
    if (idx < total) {
        int i = idx >> logF;
        int f = idx & ((1 << logF) - 1);
        float r = S[idx] * g_sn[i];
        if (b) r += b[f];
        D[idx] = r;
    }
}

// ---------------------------------------------------------------------------
// Edge scatter-add: DST[dst[e], :] += SRC[src[e], :] * norm[e]
// One thread per (edge, 4-float chunk). logC = log2(F/4).
// ---------------------------------------------------------------------------
template <int SSEL, int DSEL>
__global__ void k_scatter(const float* __restrict__ Sext,
                          float* __restrict__ Dext,
                          int e_cnt, int F, int logC) {
    const float* S = pickc<SSEL>(Sext);
    float*       D = pick<DSEL>(Dext);
    long long idx = (long long)blockIdx.x * blockDim.x + threadIdx.x;
    int e = (int)(idx >> logC);
    if (e >= e_cnt) return;
    int c = ((int)idx & ((1 << logC) - 1)) << 2;

    int s = g_src[e];
    int d = g_dst[e];
    float w = g_norm[e];
    float4 v = *(const float4*)(S + (size_t)s * F + c);
    float* o = D + (size_t)d * F + c;
    atomicAdd(o + 0, v.x * w);
    atomicAdd(o + 1, v.y * w);
    atomicAdd(o + 2, v.z * w);
    atomicAdd(o + 3, v.w * w);
}

// ---------------------------------------------------------------------------
static inline int ceil_div(int a, int b) { return (a + b - 1) / b; }
static inline unsigned sc_blocks(long long e, int F, int tpb) {
    long long tot = e * (F / 4);
    return (unsigned)((tot + tpb - 1) / tpb);
}

extern "C" void kernel_launch(void* const* d_in, const int* in_sizes, int n_in,
                              void* d_out, int out_size) {
    const float* features = (const float*)d_in[0];   // [N,1024]
    const void*  edge_idx = d_in[1];                 // [2,E] int32 or int64
    const float* W1       = (const float*)d_in[2];   // [512,1024]
    const float* b1       = (const float*)d_in[3];
    const float* W2       = (const float*)d_in[4];   // [128,512]
    const float* b2       = (const float*)d_in[5];
    const float* b3       = (const float*)d_in[6];
    const float* b4       = (const float*)d_in[7];
    const float* head1    = (const float*)d_in[8];   // [128,128]

    const int n = in_sizes[0] / IN_DIM;   // 20000
    const int e = in_sizes[1] / 2;        // 160000

    float* out = (float*)d_out;
    float* z_out  = out;                            // [N,128]
    float* h2_out = out + (size_t)n * OUT_DIM;      // [N,128]
    float* h4_out = out + (size_t)n * OUT_DIM * 2;  // [N,1024]

    const int TPB = 256;
    dim3 blk(256);

    // ---- preprocessing ----
    k_probe_dtype<<<1, 32>>>((const int*)edge_idx);
    k_deg_init<<<ceil_div(n, TPB), TPB>>>(n);
    k_deg_edges<<<ceil_div(e, TPB), TPB>>>(edge_idx, e, n);
    k_dinv<<<ceil_div(n, TPB), TPB>>>(n);
    k_edge_prep<<<ceil_div(e, TPB), TPB>>>(edge_idx, e, n);

    // ---- layer 1: g_T = X @ W1^T [N,512]; h1 = agg(g_T) + b1 -> g_H ----
    {
        dim3 grid(HID_DIM / BN, ceil_div(n, BM));
        k_sgemm<1, 0, 1><<<grid, blk>>>(n, HID_DIM, IN_DIM, features, W1, nullptr, nullptr);
        k_init_self<1, 2><<<ceil_div(n * HID_DIM, TPB), TPB>>>(nullptr, nullptr, b1, n, 9);
        k_scatter<1, 2><<<sc_blocks(e, HID_DIM, TPB), TPB>>>(nullptr, nullptr, e, HID_DIM, 7);
    }

    // ---- layer 2: g_T = h1 @ W2^T [N,128]; h2 = agg(g_T) + b2 -> h2_out ----
    {
        dim3 grid(OUT_DIM / BN, ceil_div(n, BM));
        k_sgemm<1, 2, 1><<<grid, blk>>>(n, OUT_DIM, HID_DIM, nullptr, W2, nullptr, nullptr);
        k_init_self<1, 0><<<ceil_div(n * OUT_DIM, TPB), TPB>>>(nullptr, h2_out, b2, n, 7);
        k_scatter<1, 0><<<sc_blocks(e, OUT_DIM, TPB), TPB>>>(nullptr, h2_out, e, OUT_DIM, 5);
    }

    // ---- head: z = h2 @ head1 -> z_out ----
    {
        dim3 grid(OUT_DIM / BN, ceil_div(n, BM));
        k_sgemm<0, 0, 0><<<grid, blk>>>(n, OUT_DIM, OUT_DIM, h2_out, head1, z_out, nullptr);
    }

    // ---- layer 3 (agg-first): g_T = Az [N,128]; h3 = g_T @ W2 + b3 -> g_H ----
    {
        k_init_self<0, 1><<<ceil_div(n * OUT_DIM, TPB), TPB>>>(z_out, nullptr, nullptr, n, 7);
        k_scatter<0, 1><<<sc_blocks(e, OUT_DIM, TPB), TPB>>>(z_out, nullptr, e, OUT_DIM, 5);
        dim3 grid(HID_DIM / BN, ceil_div(n, BM));
        k_sgemm<0, 1, 2><<<grid, blk>>>(n, HID_DIM, OUT_DIM, nullptr, W2, nullptr, b3);
    }

    // ---- layer 4 (agg-first): g_T = A h3 [N,512]; h4 = g_T @ W1 + b4 -> h4_out ----
    {
        k_init_self<2, 1><<<ceil_div(n * HID_DIM, TPB), TPB>>>(nullptr, nullptr, nullptr, n, 9);
        k_scatter<2, 1><<<sc_blocks(e, HID_DIM, TPB), TPB>>>(nullptr, nullptr, e, HID_DIM, 7);
        dim3 grid(IN_DIM / BN, ceil_div(n, BM));
        k_sgemm<0, 1, 0><<<grid, blk>>>(n, IN_DIM, HID_DIM, nullptr, W1, h4_out, b4);
    }

    (void)n_in; (void)out_size;
}

// round 4
// speedup vs baseline: 2.3211x; 2.3211x over previous
#include <cuda_runtime.h>
#include <cuda_bf16.h>
#include <cstdint>

// ---------------------------------------------------------------------------
// GAE 4-layer GCN autoencoder, algebraically fused:
//   W21 = W2 @ W1                      [128,1024]   (once, tiny)
//   u2  = W2 @ b1                      [128]
//   u4  = b3^T @ W1                    [1024]
//   c   = Ahat @ 1                     [N]  (c_i = sn_i + sum_in norm)
//   P   = X @ W21^T                    [N,128]
//   h2  = Ahat(Ahat P) + c (x) u2 + b2          -> out[N*128 .. ]
//   z   = h2 @ head1                            -> out[0 .. ]
//   h4  = (Ahat(Ahat z)) @ W21 + c (x) u4 + b4  -> out[N*256 .. ]
// All scatters run at width 128. GEMM FLOPs: 48 GF -> ~11 GF.
// ---------------------------------------------------------------------------

#define N_NODES 20000
#define IN_DIM  1024
#define HID_DIM 512
#define OUT_DIM 128
#define N_EDGES 160000

__device__ alignas(16) float g_T[(size_t)N_NODES * OUT_DIM];    // scratch (128 wide)
__device__ alignas(16) float g_H[(size_t)N_NODES * OUT_DIM];    // scratch (128 wide)
__device__ alignas(16) float g_W21[(size_t)OUT_DIM * IN_DIM];   // W2@W1
__device__ alignas(16) float g_u2[OUT_DIM];
__device__ alignas(16) float g_u4[IN_DIM];
__device__ float g_deg[N_NODES];
__device__ float g_dinv[N_NODES];
__device__ float g_sn[N_NODES];
__device__ float g_c[N_NODES];
__device__ int   g_src[N_EDGES];
__device__ int   g_dst[N_EDGES];
__device__ float g_norm[N_EDGES];
__device__ int   g_is64;

// pointer selector: 0 = external, 1 = g_T, 2 = g_H, 3 = g_W21
template <int SEL>
__device__ __forceinline__ float* pick(float* ext) {
    if (SEL == 1) return g_T;
    if (SEL == 2) return g_H;
    if (SEL == 3) return g_W21;
    return ext;
}
template <int SEL>
__device__ __forceinline__ const float* pickc(const float* ext) {
    if (SEL == 1) return g_T;
    if (SEL == 2) return g_H;
    if (SEL == 3) return g_W21;
    return ext;
}

// ---------------------------------------------------------------------------
// Edge-index dtype probe (int64 with values < 2^31 => zero odd int32 words)
// ---------------------------------------------------------------------------
__global__ void k_probe_dtype(const int* __restrict__ ei32) {
    if (threadIdx.x == 0 && blockIdx.x == 0) {
        int z = (ei32[1] == 0) & (ei32[3] == 0) & (ei32[5] == 0) &
                (ei32[7] == 0) & (ei32[9] == 0) & (ei32[11] == 0);
        g_is64 = z;
    }
}

__device__ __forceinline__ int load_idx(const void* ei, int e_cnt, int row, int e) {
    if (g_is64) return (int)((const long long*)ei)[(size_t)row * e_cnt + e];
    return ((const int*)ei)[(size_t)row * e_cnt + e];
}

// ---------------------------------------------------------------------------
// Preprocessing
// ---------------------------------------------------------------------------
__global__ void k_deg_init(int n) {
    int i = blockIdx.x * blockDim.x + threadIdx.x;
    if (i < n) g_deg[i] = 1.0f;  // self loop
}

__global__ void k_deg_edges(const void* __restrict__ ei, int e_cnt, int n) {
    int e = blockIdx.x * blockDim.x + threadIdx.x;
    if (e < e_cnt) {
        int d = load_idx(ei, e_cnt, 1, e);
        if ((unsigned)d < (unsigned)n) atomicAdd(&g_deg[d], 1.0f);
    }
}

__global__ void k_dinv(int n) {
    int i = blockIdx.x * blockDim.x + threadIdx.x;
    if (i < n) {
        float r = rsqrtf(g_deg[i]);
        g_dinv[i] = r;
        g_sn[i] = r * r;
        g_c[i]  = r * r;  // c starts with self-loop contribution
    }
}

__global__ void k_edge_prep(const void* __restrict__ ei, int e_cnt, int n) {
    int e = blockIdx.x * blockDim.x + threadIdx.x;
    if (e < e_cnt) {
        int s = load_idx(ei, e_cnt, 0, e);
        int d = load_idx(ei, e_cnt, 1, e);
        if ((unsigned)s >= (unsigned)n) s = 0;
        if ((unsigned)d >= (unsigned)n) d = 0;
        float w = g_dinv[s] * g_dinv[d];
        g_src[e] = s;
        g_dst[e] = d;
        g_norm[e] = w;
        atomicAdd(&g_c[d], w);
    }
}

// ---------------------------------------------------------------------------
// Small vector precomputes
// ---------------------------------------------------------------------------
__global__ void k_u2(const float* __restrict__ W2, const float* __restrict__ b1) {
    int o = blockIdx.x * blockDim.x + threadIdx.x;
    if (o < OUT_DIM) {
        float s = 0.f;
        for (int k = 0; k < HID_DIM; k++) s += W2[(size_t)o * HID_DIM + k] * b1[k];
        g_u2[o] = s;
    }
}

__global__ void k_u4(const float* __restrict__ W1, const float* __restrict__ b3) {
    int f = blockIdx.x * blockDim.x + threadIdx.x;
    if (f < IN_DIM) {
        float s = 0.f;
        for (int k = 0; k < HID_DIM; k++) s += b3[k] * W1[(size_t)k * IN_DIM + f];
        g_u4[f] = s;
    }
}

// ---------------------------------------------------------------------------
// SGEMM: C[M,Nn] = A[M,K] @ op(B) + (bias? bias:0) + (CORR4? c[m]*u4[n]:0)
//   TB=1: B is [Nn,K] row-major;  TB=0: B is [K,Nn] row-major
// K % 8 == 0, Nn % 128 == 0; M guarded.
// ---------------------------------------------------------------------------
#define BM 128
#define BN 128
#define BK 8
#define TM 8
#define TN 8

template <int TB, int ASEL, int BSEL, int CSEL, int CORR4>
__global__ __launch_bounds__(256)
void k_sgemm(int M, int Nn, int K,
             const float* __restrict__ Aext,
             const float* __restrict__ Bext,
             float* __restrict__ Cext,
             const float* __restrict__ bias) {
    const float* A = pickc<ASEL>(Aext);
    const float* B = pickc<BSEL>(Bext);
    float*       C = pick<CSEL>(Cext);

    __shared__ float As[BK][BM];
    __shared__ float Bs[BK][BN];

    const int bx = blockIdx.x;
    const int by = blockIdx.y;
    const int tid = threadIdx.x;

    const int tcol = tid % (BN / TN);
    const int trow = tid / (BN / TN);

    float acc[TM][TN];
#pragma unroll
    for (int i = 0; i < TM; i++)
#pragma unroll
        for (int j = 0; j < TN; j++) acc[i][j] = 0.0f;

    const int aRow = tid >> 1;
    const int aCol = (tid & 1) << 2;

    for (int k0 = 0; k0 < K; k0 += BK) {
        {
            int m = by * BM + aRow;
            float4 av = make_float4(0.f, 0.f, 0.f, 0.f);
            if (m < M) av = *(const float4*)(A + (size_t)m * K + k0 + aCol);
            As[aCol + 0][aRow] = av.x;
            As[aCol + 1][aRow] = av.y;
            As[aCol + 2][aRow] = av.z;
            As[aCol + 3][aRow] = av.w;
        }
        if (TB) {
            int nn = bx * BN + aRow;
            float4 bv = *(const float4*)(B + (size_t)nn * K + k0 + aCol);
            Bs[aCol + 0][aRow] = bv.x;
            Bs[aCol + 1][aRow] = bv.y;
            Bs[aCol + 2][aRow] = bv.z;
            Bs[aCol + 3][aRow] = bv.w;
        } else {
            int kk = tid >> 5;
            int nn = (tid & 31) << 2;
            float4 bv = *(const float4*)(B + (size_t)(k0 + kk) * Nn + bx * BN + nn);
            *(float4*)&Bs[kk][nn] = bv;
        }
        __syncthreads();

#pragma unroll
        for (int k = 0; k < BK; k++) {
            float ra[TM], rb[TN];
#pragma unroll
            for (int i = 0; i < TM; i++) ra[i] = As[k][trow * TM + i];
#pragma unroll
            for (int j = 0; j < TN; j++) rb[j] = Bs[k][tcol * TN + j];
#pragma unroll
            for (int i = 0; i < TM; i++)
#pragma unroll
                for (int j = 0; j < TN; j++) acc[i][j] += ra[i] * rb[j];
        }
        __syncthreads();
    }

    float addc[TN];
#pragma unroll
    for (int j = 0; j < TN; j++) {
        int nn = bx * BN + tcol * TN + j;
        addc[j] = bias ? bias[nn] : 0.0f;
    }

#pragma unroll
    for (int i = 0; i < TM; i++) {
        int m = by * BM + trow * TM + i;
        if (m < M) {
            float rowadd[TN];
#pragma unroll
            for (int j = 0; j < TN; j++) rowadd[j] = addc[j];
            if (CORR4) {
                float ci = g_c[m];
#pragma unroll
                for (int j = 0; j < TN; j++)
                    rowadd[j] += ci * g_u4[bx * BN + tcol * TN + j];
            }
            float* cp = C + (size_t)m * Nn + bx * BN + tcol * TN;
            *(float4*)(cp + 0) = make_float4(acc[i][0] + rowadd[0], acc[i][1] + rowadd[1],
                                             acc[i][2] + rowadd[2], acc[i][3] + rowadd[3]);
            *(float4*)(cp + 4) = make_float4(acc[i][4] + rowadd[4], acc[i][5] + rowadd[5],
                                             acc[i][6] + rowadd[6], acc[i][7] + rowadd[7]);
        }
    }
}

// ---------------------------------------------------------------------------
// Init: D[i,f] = sn[i]*S[i,f] (+ CORR: c[i]*u2[f] + b[f])   — self-loop term
// ---------------------------------------------------------------------------
template <int SSEL, int DSEL, int CORR>
__global__ void k_init(const float* __restrict__ Sext,
                       float* __restrict__ Dext,
                       const float* __restrict__ b,
                       int n, int logF) {
    const float* S = pickc<SSEL>(Sext);
    float*       D = pick<DSEL>(Dext);
    int idx = blockIdx.x * blockDim.x + threadIdx.x;
    int total = n << logF;
    if (idx < total) {
        int i = idx >> logF;
        int f = idx & ((1 << logF) - 1);
        float r = S[idx] * g_sn[i];
        if (CORR) r += g_c[i] * g_u2[f] + b[f];
        D[idx] = r;
    }
}

// ---------------------------------------------------------------------------
// Edge scatter-add at width 128: D[dst,:] += S[src,:] * norm
// One thread per (edge, float4 chunk): 32 chunks/edge.
// ---------------------------------------------------------------------------
template <int SSEL, int DSEL>
__global__ void k_scatter(const float* __restrict__ Sext,
                          float* __restrict__ Dext,
                          int e_cnt) {
    const float* S = pickc<SSEL>(Sext);
    float*       D = pick<DSEL>(Dext);
    long long idx = (long long)blockIdx.x * blockDim.x + threadIdx.x;
    int e = (int)(idx >> 5);
    if (e >= e_cnt) return;
    int c = ((int)idx & 31) << 2;

    int s = g_src[e];
    int d = g_dst[e];
    float w = g_norm[e];
    float4 v = *(const float4*)(S + (size_t)s * OUT_DIM + c);
    float* o = D + (size_t)d * OUT_DIM + c;
    atomicAdd(o + 0, v.x * w);
    atomicAdd(o + 1, v.y * w);
    atomicAdd(o + 2, v.z * w);
    atomicAdd(o + 3, v.w * w);
}

// ---------------------------------------------------------------------------
static inline int ceil_div(int a, int b) { return (a + b - 1) / b; }

extern "C" void kernel_launch(void* const* d_in, const int* in_sizes, int n_in,
                              void* d_out, int out_size) {
    const float* features = (const float*)d_in[0];   // [N,1024]
    const void*  edge_idx = d_in[1];                 // [2,E] int32 or int64
    const float* W1       = (const float*)d_in[2];   // [512,1024]
    const float* b1       = (const float*)d_in[3];
    const float* W2       = (const float*)d_in[4];   // [128,512]
    const float* b2       = (const float*)d_in[5];
    const float* b3       = (const float*)d_in[6];
    const float* b4       = (const float*)d_in[7];
    const float* head1    = (const float*)d_in[8];   // [128,128]

    const int n = in_sizes[0] / IN_DIM;   // 20000
    const int e = in_sizes[1] / 2;        // 160000

    float* out = (float*)d_out;
    float* z_out  = out;                            // [N,128]
    float* h2_out = out + (size_t)n * OUT_DIM;      // [N,128]
    float* h4_out = out + (size_t)n * OUT_DIM * 2;  // [N,1024]

    const int TPB = 256;
    dim3 blk(256);
    unsigned scb = (unsigned)(((long long)e * 32 + TPB - 1) / TPB);

    // ---- preprocessing ----
    k_probe_dtype<<<1, 32>>>((const int*)edge_idx);
    k_deg_init<<<ceil_div(n, TPB), TPB>>>(n);
    k_deg_edges<<<ceil_div(e, TPB), TPB>>>(edge_idx, e, n);
    k_dinv<<<ceil_div(n, TPB), TPB>>>(n);
    k_edge_prep<<<ceil_div(e, TPB), TPB>>>(edge_idx, e, n);

    // ---- weight precomputes ----
    {
        // W21 = W2 @ W1 : [128,1024], K=512
        dim3 grid(IN_DIM / BN, 1);
        k_sgemm<0, 0, 0, 3, 0><<<grid, blk>>>(OUT_DIM, IN_DIM, HID_DIM, W2, W1, nullptr, nullptr);
        k_u2<<<1, 128>>>(W2, b1);
        k_u4<<<ceil_div(IN_DIM, TPB), TPB>>>(W1, b3);
    }

    // ---- P = X @ W21^T [N,128] -> g_T ----
    {
        dim3 grid(OUT_DIM / BN, ceil_div(n, BM));
        k_sgemm<1, 0, 3, 1, 0><<<grid, blk>>>(n, OUT_DIM, IN_DIM, features, nullptr, nullptr, nullptr);
    }

    // ---- S1 = Ahat P -> g_H ----
    k_init<1, 2, 0><<<ceil_div(n * OUT_DIM, TPB), TPB>>>(nullptr, nullptr, nullptr, n, 7);
    k_scatter<1, 2><<<scb, TPB>>>(nullptr, nullptr, e);

    // ---- h2 = Ahat S1 + c(x)u2 + b2 -> h2_out ----
    k_init<2, 0, 1><<<ceil_div(n * OUT_DIM, TPB), TPB>>>(nullptr, h2_out, b2, n, 7);
    k_scatter<2, 0><<<scb, TPB>>>(nullptr, h2_out, e);

    // ---- z = h2 @ head1 -> z_out ----
    {
        dim3 grid(OUT_DIM / BN, ceil_div(n, BM));
        k_sgemm<0, 0, 0, 0, 0><<<grid, blk>>>(n, OUT_DIM, OUT_DIM, h2_out, head1, z_out, nullptr);
    }

    // ---- S2 = Ahat z -> g_T ----
    k_init<0, 1, 0><<<ceil_div(n * OUT_DIM, TPB), TPB>>>(z_out, nullptr, nullptr, n, 7);
    k_scatter<0, 1><<<scb, TPB>>>(z_out, nullptr, e);

    // ---- Q = Ahat S2 -> g_H ----
    k_init<1, 2, 0><<<ceil_div(n * OUT_DIM, TPB), TPB>>>(nullptr, nullptr, nullptr, n, 7);
    k_scatter<1, 2><<<scb, TPB>>>(nullptr, nullptr, e);

    // ---- h4 = Q @ W21 + c(x)u4 + b4 -> h4_out ----
    {
        dim3 grid(IN_DIM / BN, ceil_div(n, BM));
        k_sgemm<0, 2, 3, 0, 1><<<grid, blk>>>(n, IN_DIM, OUT_DIM, nullptr, nullptr, h4_out, b4);
    }

    (void)n_in; (void)out_size;
}

// round 5
// speedup vs baseline: 2.6285x; 1.1324x over previous
#include <cuda_runtime.h>
#include <cuda_bf16.h>
#include <cstdint>

// ---------------------------------------------------------------------------
// GAE 4-layer GCN autoencoder, algebraically fused + CSR-gather aggregation.
//   W21 = W2 @ W1  [128,1024], u2 = W2@b1 [128], u4 = b3^T@W1 [1024]
//   c   = Ahat @ 1 [N]
//   P   = X @ W21^T            [N,128]
//   h2  = Ahat(Ahat P) + c(x)u2 + b2
//   z   = h2 @ head1
//   h4  = Ahat(Ahat z) @ W21 + c(x)u4 + b4
// Aggregation = warp-per-node CSR gather (no atomics, init fused).
// ---------------------------------------------------------------------------

#define N_NODES 20000
#define IN_DIM  1024
#define HID_DIM 512
#define OUT_DIM 128
#define N_EDGES 160000

__device__ alignas(16) float g_T[(size_t)N_NODES * OUT_DIM];
__device__ alignas(16) float g_H[(size_t)N_NODES * OUT_DIM];
__device__ alignas(16) float g_W21[(size_t)OUT_DIM * IN_DIM];
__device__ alignas(16) float g_u2[OUT_DIM];
__device__ alignas(16) float g_u4[IN_DIM];
__device__ float g_dinv[N_NODES];
__device__ float g_sn[N_NODES];
__device__ float g_c[N_NODES];
__device__ int   g_cnt[N_NODES];
__device__ int   g_off[N_NODES + 1];
__device__ int   g_cur[N_NODES];
__device__ int2  g_adj[N_EDGES];     // .x = src, .y = bits(norm)
__device__ int   g_is64;

// pointer selector: 0 = external, 1 = g_T, 2 = g_H, 3 = g_W21
template <int SEL>
__device__ __forceinline__ float* pick(float* ext) {
    if (SEL == 1) return g_T;
    if (SEL == 2) return g_H;
    if (SEL == 3) return g_W21;
    return ext;
}
template <int SEL>
__device__ __forceinline__ const float* pickc(const float* ext) {
    if (SEL == 1) return g_T;
    if (SEL == 2) return g_H;
    if (SEL == 3) return g_W21;
    return ext;
}

// ---------------------------------------------------------------------------
// Edge-index dtype probe (int64 values < 2^31 => odd int32 words are zero)
// ---------------------------------------------------------------------------
__global__ void k_probe_dtype(const int* __restrict__ ei32) {
    if (threadIdx.x == 0 && blockIdx.x == 0) {
        int z = (ei32[1] == 0) & (ei32[3] == 0) & (ei32[5] == 0) &
                (ei32[7] == 0) & (ei32[9] == 0) & (ei32[11] == 0);
        g_is64 = z;
    }
}

__device__ __forceinline__ int load_idx(const void* ei, int e_cnt, int row, int e) {
    if (g_is64) return (int)((const long long*)ei)[(size_t)row * e_cnt + e];
    return ((const int*)ei)[(size_t)row * e_cnt + e];
}

// ---------------------------------------------------------------------------
// CSR build
// ---------------------------------------------------------------------------
__global__ void k_zero_cnt(int n) {
    int i = blockIdx.x * blockDim.x + threadIdx.x;
    if (i < n) g_cnt[i] = 0;
}

__global__ void k_count(const void* __restrict__ ei, int e_cnt, int n) {
    int e = blockIdx.x * blockDim.x + threadIdx.x;
    if (e < e_cnt) {
        int d = load_idx(ei, e_cnt, 1, e);
        if ((unsigned)d < (unsigned)n) atomicAdd(&g_cnt[d], 1);
    }
}

__global__ void k_dinv(int n) {
    int i = blockIdx.x * blockDim.x + threadIdx.x;
    if (i < n) {
        float r = rsqrtf((float)(g_cnt[i] + 1));  // +1 self loop
        g_dinv[i] = r;
        g_sn[i] = r * r;
    }
}

// single-block exclusive scan of g_cnt -> g_off (+ g_cur copy)
__global__ void k_scan(int n) {
    __shared__ int sh[1024];
    __shared__ int carry_s;
    int tid = threadIdx.x;
    if (tid == 0) { carry_s = 0; g_off[0] = 0; }
    __syncthreads();
    for (int base = 0; base < n; base += 1024) {
        int i = base + tid;
        int v = (i < n) ? g_cnt[i] : 0;
        sh[tid] = v;
        __syncthreads();
        for (int s = 1; s < 1024; s <<= 1) {
            int t = (tid >= s) ? sh[tid - s] : 0;
            __syncthreads();
            sh[tid] += t;
            __syncthreads();
        }
        int carry = carry_s;
        if (i < n) {
            g_off[i + 1] = carry + sh[tid];
            g_cur[i]     = carry + sh[tid] - v;
        }
        __syncthreads();
        if (tid == 0) carry_s = carry + sh[1023];
        __syncthreads();
    }
}

__global__ void k_fill(const void* __restrict__ ei, int e_cnt, int n) {
    int e = blockIdx.x * blockDim.x + threadIdx.x;
    if (e < e_cnt) {
        int s = load_idx(ei, e_cnt, 0, e);
        int d = load_idx(ei, e_cnt, 1, e);
        if ((unsigned)s >= (unsigned)n) s = 0;
        if ((unsigned)d >= (unsigned)n) d = 0;
        float w = g_dinv[s] * g_dinv[d];
        int pos = atomicAdd(&g_cur[d], 1);
        g_adj[pos] = make_int2(s, __float_as_int(w));
    }
}

__global__ void k_c(int n) {
    int i = blockIdx.x * blockDim.x + threadIdx.x;
    if (i < n) {
        float acc = g_sn[i];
        int beg = g_off[i], end = g_off[i + 1];
        for (int p = beg; p < end; p++) acc += __int_as_float(g_adj[p].y);
        g_c[i] = acc;
    }
}

// ---------------------------------------------------------------------------
// Small vector precomputes
// ---------------------------------------------------------------------------
__global__ void k_u2(const float* __restrict__ W2, const float* __restrict__ b1) {
    int o = blockIdx.x * blockDim.x + threadIdx.x;
    if (o < OUT_DIM) {
        float s = 0.f;
        for (int k = 0; k < HID_DIM; k++) s += W2[(size_t)o * HID_DIM + k] * b1[k];
        g_u2[o] = s;
    }
}

__global__ void k_u4(const float* __restrict__ W1, const float* __restrict__ b3) {
    int f = blockIdx.x * blockDim.x + threadIdx.x;
    if (f < IN_DIM) {
        float s = 0.f;
        for (int k = 0; k < HID_DIM; k++) s += b3[k] * W1[(size_t)k * IN_DIM + f];
        g_u4[f] = s;
    }
}

// ---------------------------------------------------------------------------
// SGEMM: C[M,Nn] = A[M,K] @ op(B) + bias + (CORR4? c[m]*u4[n]:0)
//   TB=1: B is [Nn,K] row-major;  TB=0: B is [K,Nn] row-major
//   BMv in {64,128}. 256 threads. K%8==0, Nn%128==0. M guarded.
// ---------------------------------------------------------------------------
#define BN 128
#define BK 8
#define TN 8

template <int TB, int ASEL, int BSEL, int CSEL, int CORR4, int BMv>
__global__ __launch_bounds__(256)
void k_sgemm(int M, int Nn, int K,
             const float* __restrict__ Aext,
             const float* __restrict__ Bext,
             float* __restrict__ Cext,
             const float* __restrict__ bias) {
    constexpr int TMv = BMv / 16;
    const float* A = pickc<ASEL>(Aext);
    const float* B = pickc<BSEL>(Bext);
    float*       C = pick<CSEL>(Cext);

    __shared__ float As[BK][BMv];
    __shared__ float Bs[BK][BN];

    const int bx = blockIdx.x;
    const int by = blockIdx.y;
    const int tid = threadIdx.x;

    const int tcol = tid % (BN / TN);  // 0..15
    const int trow = tid / (BN / TN);  // 0..15

    float acc[TMv][TN];
#pragma unroll
    for (int i = 0; i < TMv; i++)
#pragma unroll
        for (int j = 0; j < TN; j++) acc[i][j] = 0.0f;

    for (int k0 = 0; k0 < K; k0 += BK) {
        // --- A tile: BMv x 8 floats ---
        if (BMv == 128) {
            int aRow = tid >> 1;
            int aCol = (tid & 1) << 2;
            int m = by * BMv + aRow;
            float4 av = make_float4(0.f, 0.f, 0.f, 0.f);
            if (m < M) av = *(const float4*)(A + (size_t)m * K + k0 + aCol);
            As[aCol + 0][aRow] = av.x;
            As[aCol + 1][aRow] = av.y;
            As[aCol + 2][aRow] = av.z;
            As[aCol + 3][aRow] = av.w;
        } else {  // BMv == 64: 128 float4 loads, threads 0..127
            if (tid < 128) {
                int aRow = tid >> 1;
                int aCol = (tid & 1) << 2;
                int m = by * BMv + aRow;
                float4 av = make_float4(0.f, 0.f, 0.f, 0.f);
                if (m < M) av = *(const float4*)(A + (size_t)m * K + k0 + aCol);
                As[aCol + 0][aRow] = av.x;
                As[aCol + 1][aRow] = av.y;
                As[aCol + 2][aRow] = av.z;
                As[aCol + 3][aRow] = av.w;
            }
        }
        // --- B tile: 128 x 8 ---
        if (TB) {
            int nRow = tid >> 1;
            int nCol = (tid & 1) << 2;
            int nn = bx * BN + nRow;
            float4 bv = *(const float4*)(B + (size_t)nn * K + k0 + nCol);
            Bs[nCol + 0][nRow] = bv.x;
            Bs[nCol + 1][nRow] = bv.y;
            Bs[nCol + 2][nRow] = bv.z;
            Bs[nCol + 3][nRow] = bv.w;
        } else {
            int kk = tid >> 5;
            int nn = (tid & 31) << 2;
            float4 bv = *(const float4*)(B + (size_t)(k0 + kk) * Nn + bx * BN + nn);
            *(float4*)&Bs[kk][nn] = bv;
        }
        __syncthreads();

#pragma unroll
        for (int k = 0; k < BK; k++) {
            float ra[TMv], rb[TN];
#pragma unroll
            for (int i = 0; i < TMv; i++) ra[i] = As[k][trow * TMv + i];
#pragma unroll
            for (int j = 0; j < TN; j++) rb[j] = Bs[k][tcol * TN + j];
#pragma unroll
            for (int i = 0; i < TMv; i++)
#pragma unroll
                for (int j = 0; j < TN; j++) acc[i][j] += ra[i] * rb[j];
        }
        __syncthreads();
    }

    float addc[TN];
#pragma unroll
    for (int j = 0; j < TN; j++) {
        int nn = bx * BN + tcol * TN + j;
        addc[j] = bias ? bias[nn] : 0.0f;
    }

#pragma unroll
    for (int i = 0; i < TMv; i++) {
        int m = by * BMv + trow * TMv + i;
        if (m < M) {
            float rowadd[TN];
#pragma unroll
            for (int j = 0; j < TN; j++) rowadd[j] = addc[j];
            if (CORR4) {
                float ci = g_c[m];
#pragma unroll
                for (int j = 0; j < TN; j++)
                    rowadd[j] += ci * g_u4[bx * BN + tcol * TN + j];
            }
            float* cp = C + (size_t)m * Nn + bx * BN + tcol * TN;
            *(float4*)(cp + 0) = make_float4(acc[i][0] + rowadd[0], acc[i][1] + rowadd[1],
                                             acc[i][2] + rowadd[2], acc[i][3] + rowadd[3]);
            *(float4*)(cp + 4) = make_float4(acc[i][4] + rowadd[4], acc[i][5] + rowadd[5],
                                             acc[i][6] + rowadd[6], acc[i][7] + rowadd[7]);
        }
    }
}

// ---------------------------------------------------------------------------
// Aggregation (warp-per-node CSR gather), width 128:
//   D[i,:] = sn[i]*S[i,:] + sum_in w*S[src,:]  (+ CORR: c[i]*u2[:] + b[:])
// ---------------------------------------------------------------------------
template <int SSEL, int DSEL, int CORR>
__global__ __launch_bounds__(256)
void k_agg(const float* __restrict__ Sext,
           float* __restrict__ Dext,
           const float* __restrict__ b,
           int n) {
    int gw = (blockIdx.x * 256 + threadIdx.x) >> 5;
    if (gw >= n) return;
    int lane = threadIdx.x & 31;
    const float* S = pickc<SSEL>(Sext);
    float*       D = pick<DSEL>(Dext);

    int beg = g_off[gw];
    int end = g_off[gw + 1];
    float sn = g_sn[gw];
    float4 v = *(const float4*)(S + (size_t)gw * OUT_DIM + lane * 4);
    float4 acc = make_float4(sn * v.x, sn * v.y, sn * v.z, sn * v.w);

    for (int p = beg; p < end; p++) {
        int2 pr = g_adj[p];
        float w = __int_as_float(pr.y);
        float4 u = *(const float4*)(S + (size_t)pr.x * OUT_DIM + lane * 4);
        acc.x += w * u.x;
        acc.y += w * u.y;
        acc.z += w * u.z;
        acc.w += w * u.w;
    }

    if (CORR) {
        float ci = g_c[gw];
        int f = lane * 4;
        acc.x += ci * g_u2[f + 0] + b[f + 0];
        acc.y += ci * g_u2[f + 1] + b[f + 1];
        acc.z += ci * g_u2[f + 2] + b[f + 2];
        acc.w += ci * g_u2[f + 3] + b[f + 3];
    }
    *(float4*)(D + (size_t)gw * OUT_DIM + lane * 4) = acc;
}

// ---------------------------------------------------------------------------
static inline int ceil_div(int a, int b) { return (a + b - 1) / b; }

extern "C" void kernel_launch(void* const* d_in, const int* in_sizes, int n_in,
                              void* d_out, int out_size) {
    const float* features = (const float*)d_in[0];   // [N,1024]
    const void*  edge_idx = d_in[1];                 // [2,E] int32 or int64
    const float* W1       = (const float*)d_in[2];   // [512,1024]
    const float* b1       = (const float*)d_in[3];
    const float* W2       = (const float*)d_in[4];   // [128,512]
    const float* b2       = (const float*)d_in[5];
    const float* b3       = (const float*)d_in[6];
    const float* b4       = (const float*)d_in[7];
    const float* head1    = (const float*)d_in[8];   // [128,128]

    const int n = in_sizes[0] / IN_DIM;   // 20000
    const int e = in_sizes[1] / 2;        // 160000

    float* out = (float*)d_out;
    float* z_out  = out;
    float* h2_out = out + (size_t)n * OUT_DIM;
    float* h4_out = out + (size_t)n * OUT_DIM * 2;

    const int TPB = 256;
    dim3 blk(256);
    int aggb = ceil_div(n * 32, TPB);

    // ---- CSR + norm preprocessing ----
    k_probe_dtype<<<1, 32>>>((const int*)edge_idx);
    k_zero_cnt<<<ceil_div(n, TPB), TPB>>>(n);
    k_count<<<ceil_div(e, TPB), TPB>>>(edge_idx, e, n);
    k_dinv<<<ceil_div(n, TPB), TPB>>>(n);
    k_scan<<<1, 1024>>>(n);
    k_fill<<<ceil_div(e, TPB), TPB>>>(edge_idx, e, n);
    k_c<<<ceil_div(n, TPB), TPB>>>(n);

    // ---- weight precomputes ----
    {
        dim3 grid(IN_DIM / BN, 1);
        k_sgemm<0, 0, 0, 3, 0, 128><<<grid, blk>>>(OUT_DIM, IN_DIM, HID_DIM, W2, W1, nullptr, nullptr);
        k_u2<<<1, 128>>>(W2, b1);
        k_u4<<<ceil_div(IN_DIM, TPB), TPB>>>(W1, b3);
    }

    // ---- P = X @ W21^T [N,128] -> g_T (BM=64 for occupancy) ----
    {
        dim3 grid(1, ceil_div(n, 64));
        k_sgemm<1, 0, 3, 1, 0, 64><<<grid, blk>>>(n, OUT_DIM, IN_DIM, features, nullptr, nullptr, nullptr);
    }

    // ---- S1 = Ahat P -> g_H ;  h2 = Ahat S1 + c(x)u2 + b2 -> h2_out ----
    k_agg<1, 2, 0><<<aggb, blk>>>(nullptr, nullptr, nullptr, n);
    k_agg<2, 0, 1><<<aggb, blk>>>(nullptr, h2_out, b2, n);

    // ---- z = h2 @ head1 -> z_out ----
    {
        dim3 grid(1, ceil_div(n, 64));
        k_sgemm<0, 0, 0, 0, 0, 64><<<grid, blk>>>(n, OUT_DIM, OUT_DIM, h2_out, head1, z_out, nullptr);
    }

    // ---- S2 = Ahat z -> g_T ;  Q = Ahat S2 -> g_H ----
    k_agg<0, 1, 0><<<aggb, blk>>>(z_out, nullptr, nullptr, n);
    k_agg<1, 2, 0><<<aggb, blk>>>(nullptr, nullptr, nullptr, n);

    // ---- h4 = Q @ W21 + c(x)u4 + b4 -> h4_out ----
    {
        dim3 grid(IN_DIM / BN, ceil_div(n, 128));
        k_sgemm<0, 2, 3, 0, 1, 128><<<grid, blk>>>(n, IN_DIM, OUT_DIM, nullptr, nullptr, h4_out, b4);
    }

    (void)n_in; (void)out_size;
}

// round 6
// speedup vs baseline: 2.6480x; 1.0074x over previous
#include <cuda_runtime.h>
#include <cuda_bf16.h>
#include <cstdint>

// ---------------------------------------------------------------------------
// GAE 4-layer GCN autoencoder, algebraically fused + CSR-gather aggregation.
//   W21 = W2 @ W1  [128,1024], u2 = W2@b1 [128], u4 = b3^T@W1 [1024]
//   c   = Ahat @ 1 [N]
//   P   = X @ W21^T            [N,128]
//   h2  = Ahat(Ahat P) + c(x)u2 + b2
//   z   = h2 @ head1
//   h4  = Ahat(Ahat z) @ W21 + c(x)u4 + b4
// Aggregation = warp-per-node CSR gather (no atomics, init fused).
// ---------------------------------------------------------------------------

#define N_NODES 20000
#define IN_DIM  1024
#define HID_DIM 512
#define OUT_DIM 128
#define N_EDGES 160000

__device__ alignas(16) float g_T[(size_t)N_NODES * OUT_DIM];
__device__ alignas(16) float g_H[(size_t)N_NODES * OUT_DIM];
__device__ alignas(16) float g_W21[(size_t)OUT_DIM * IN_DIM];
__device__ alignas(16) float g_u2[OUT_DIM];
__device__ alignas(16) float g_u4[IN_DIM];
__device__ float g_dinv[N_NODES];
__device__ float g_sn[N_NODES];
__device__ float g_c[N_NODES];
__device__ int   g_cnt[N_NODES];
__device__ int   g_off[N_NODES + 1];
__device__ int   g_cur[N_NODES];
__device__ int2  g_adj[N_EDGES];     // .x = src, .y = bits(norm)
__device__ int   g_is64;

// pointer selector: 0 = external, 1 = g_T, 2 = g_H, 3 = g_W21
template <int SEL>
__device__ __forceinline__ float* pick(float* ext) {
    if (SEL == 1) return g_T;
    if (SEL == 2) return g_H;
    if (SEL == 3) return g_W21;
    return ext;
}
template <int SEL>
__device__ __forceinline__ const float* pickc(const float* ext) {
    if (SEL == 1) return g_T;
    if (SEL == 2) return g_H;
    if (SEL == 3) return g_W21;
    return ext;
}

// ---------------------------------------------------------------------------
// Edge-index dtype probe (int64 values < 2^31 => odd int32 words are zero)
// ---------------------------------------------------------------------------
__global__ void k_probe_dtype(const int* __restrict__ ei32) {
    if (threadIdx.x == 0 && blockIdx.x == 0) {
        int z = (ei32[1] == 0) & (ei32[3] == 0) & (ei32[5] == 0) &
                (ei32[7] == 0) & (ei32[9] == 0) & (ei32[11] == 0);
        g_is64 = z;
    }
}

__device__ __forceinline__ int load_idx(const void* ei, int e_cnt, int row, int e) {
    if (g_is64) return (int)((const long long*)ei)[(size_t)row * e_cnt + e];
    return ((const int*)ei)[(size_t)row * e_cnt + e];
}

// ---------------------------------------------------------------------------
// CSR build
// ---------------------------------------------------------------------------
__global__ void k_zero_cnt(int n) {
    int i = blockIdx.x * blockDim.x + threadIdx.x;
    if (i < n) g_cnt[i] = 0;
}

__global__ void k_count(const void* __restrict__ ei, int e_cnt, int n) {
    int e = blockIdx.x * blockDim.x + threadIdx.x;
    if (e < e_cnt) {
        int d = load_idx(ei, e_cnt, 1, e);
        if ((unsigned)d < (unsigned)n) atomicAdd(&g_cnt[d], 1);
    }
}

__global__ void k_dinv(int n) {
    int i = blockIdx.x * blockDim.x + threadIdx.x;
    if (i < n) {
        float r = rsqrtf((float)(g_cnt[i] + 1));  // +1 self loop
        g_dinv[i] = r;
        g_sn[i] = r * r;
    }
}

// single-block exclusive scan of g_cnt -> g_off (+ g_cur copy)
__global__ void k_scan(int n) {
    __shared__ int sh[1024];
    __shared__ int carry_s;
    int tid = threadIdx.x;
    if (tid == 0) { carry_s = 0; g_off[0] = 0; }
    __syncthreads();
    for (int base = 0; base < n; base += 1024) {
        int i = base + tid;
        int v = (i < n) ? g_cnt[i] : 0;
        sh[tid] = v;
        __syncthreads();
        for (int s = 1; s < 1024; s <<= 1) {
            int t = (tid >= s) ? sh[tid - s] : 0;
            __syncthreads();
            sh[tid] += t;
            __syncthreads();
        }
        int carry = carry_s;
        if (i < n) {
            g_off[i + 1] = carry + sh[tid];
            g_cur[i]     = carry + sh[tid] - v;
        }
        __syncthreads();
        if (tid == 0) carry_s = carry + sh[1023];
        __syncthreads();
    }
}

__global__ void k_fill(const void* __restrict__ ei, int e_cnt, int n) {
    int e = blockIdx.x * blockDim.x + threadIdx.x;
    if (e < e_cnt) {
        int s = load_idx(ei, e_cnt, 0, e);
        int d = load_idx(ei, e_cnt, 1, e);
        if ((unsigned)s >= (unsigned)n) s = 0;
        if ((unsigned)d >= (unsigned)n) d = 0;
        float w = g_dinv[s] * g_dinv[d];
        int pos = atomicAdd(&g_cur[d], 1);
        g_adj[pos] = make_int2(s, __float_as_int(w));
    }
}

__global__ void k_c(int n) {
    int i = blockIdx.x * blockDim.x + threadIdx.x;
    if (i < n) {
        float acc = g_sn[i];
        int beg = g_off[i], end = g_off[i + 1];
        for (int p = beg; p < end; p++) acc += __int_as_float(g_adj[p].y);
        g_c[i] = acc;
    }
}

// ---------------------------------------------------------------------------
// Small vector precomputes
// ---------------------------------------------------------------------------
__global__ void k_u2(const float* __restrict__ W2, const float* __restrict__ b1) {
    int o = blockIdx.x * blockDim.x + threadIdx.x;
    if (o < OUT_DIM) {
        float s = 0.f;
        for (int k = 0; k < HID_DIM; k++) s += W2[(size_t)o * HID_DIM + k] * b1[k];
        g_u2[o] = s;
    }
}

__global__ void k_u4(const float* __restrict__ W1, const float* __restrict__ b3) {
    int f = blockIdx.x * blockDim.x + threadIdx.x;
    if (f < IN_DIM) {
        float s = 0.f;
        for (int k = 0; k < HID_DIM; k++) s += b3[k] * W1[(size_t)k * IN_DIM + f];
        g_u4[f] = s;
    }
}

// ---------------------------------------------------------------------------
// SGEMM: C[M,Nn] = A[M,K] @ op(B) + bias + (CORR4? c[m]*u4[n]:0)
//   TB=1: B is [Nn,K] row-major;  TB=0: B is [K,Nn] row-major
//   BMv in {64,128}. 256 threads. K%8==0, Nn%128==0. M guarded.
// ---------------------------------------------------------------------------
#define BN 128
#define BK 8
#define TN 8

template <int TB, int ASEL, int BSEL, int CSEL, int CORR4, int BMv>
__global__ __launch_bounds__(256)
void k_sgemm(int M, int Nn, int K,
             const float* __restrict__ Aext,
             const float* __restrict__ Bext,
             float* __restrict__ Cext,
             const float* __restrict__ bias) {
    constexpr int TMv = BMv / 16;
    const float* A = pickc<ASEL>(Aext);
    const float* B = pickc<BSEL>(Bext);
    float*       C = pick<CSEL>(Cext);

    __shared__ float As[BK][BMv];
    __shared__ float Bs[BK][BN];

    const int bx = blockIdx.x;
    const int by = blockIdx.y;
    const int tid = threadIdx.x;

    const int tcol = tid % (BN / TN);  // 0..15
    const int trow = tid / (BN / TN);  // 0..15

    float acc[TMv][TN];
#pragma unroll
    for (int i = 0; i < TMv; i++)
#pragma unroll
        for (int j = 0; j < TN; j++) acc[i][j] = 0.0f;

    for (int k0 = 0; k0 < K; k0 += BK) {
        // --- A tile: BMv x 8 floats ---
        if (BMv == 128) {
            int aRow = tid >> 1;
            int aCol = (tid & 1) << 2;
            int m = by * BMv + aRow;
            float4 av = make_float4(0.f, 0.f, 0.f, 0.f);
            if (m < M) av = *(const float4*)(A + (size_t)m * K + k0 + aCol);
            As[aCol + 0][aRow] = av.x;
            As[aCol + 1][aRow] = av.y;
            As[aCol + 2][aRow] = av.z;
            As[aCol + 3][aRow] = av.w;
        } else {  // BMv == 64: 128 float4 loads, threads 0..127
            if (tid < 128) {
                int aRow = tid >> 1;
                int aCol = (tid & 1) << 2;
                int m = by * BMv + aRow;
                float4 av = make_float4(0.f, 0.f, 0.f, 0.f);
                if (m < M) av = *(const float4*)(A + (size_t)m * K + k0 + aCol);
                As[aCol + 0][aRow] = av.x;
                As[aCol + 1][aRow] = av.y;
                As[aCol + 2][aRow] = av.z;
                As[aCol + 3][aRow] = av.w;
            }
        }
        // --- B tile: 128 x 8 ---
        if (TB) {
            int nRow = tid >> 1;
            int nCol = (tid & 1) << 2;
            int nn = bx * BN + nRow;
            float4 bv = *(const float4*)(B + (size_t)nn * K + k0 + nCol);
            Bs[nCol + 0][nRow] = bv.x;
            Bs[nCol + 1][nRow] = bv.y;
            Bs[nCol + 2][nRow] = bv.z;
            Bs[nCol + 3][nRow] = bv.w;
        } else {
            int kk = tid >> 5;
            int nn = (tid & 31) << 2;
            float4 bv = *(const float4*)(B + (size_t)(k0 + kk) * Nn + bx * BN + nn);
            *(float4*)&Bs[kk][nn] = bv;
        }
        __syncthreads();

#pragma unroll
        for (int k = 0; k < BK; k++) {
            float ra[TMv], rb[TN];
#pragma unroll
            for (int i = 0; i < TMv; i++) ra[i] = As[k][trow * TMv + i];
#pragma unroll
            for (int j = 0; j < TN; j++) rb[j] = Bs[k][tcol * TN + j];
#pragma unroll
            for (int i = 0; i < TMv; i++)
#pragma unroll
                for (int j = 0; j < TN; j++) acc[i][j] += ra[i] * rb[j];
        }
        __syncthreads();
    }

    float addc[TN];
#pragma unroll
    for (int j = 0; j < TN; j++) {
        int nn = bx * BN + tcol * TN + j;
        addc[j] = bias ? bias[nn] : 0.0f;
    }

#pragma unroll
    for (int i = 0; i < TMv; i++) {
        int m = by * BMv + trow * TMv + i;
        if (m < M) {
            float rowadd[TN];
#pragma unroll
            for (int j = 0; j < TN; j++) rowadd[j] = addc[j];
            if (CORR4) {
                float ci = g_c[m];
#pragma unroll
                for (int j = 0; j < TN; j++)
                    rowadd[j] += ci * g_u4[bx * BN + tcol * TN + j];
            }
            float* cp = C + (size_t)m * Nn + bx * BN + tcol * TN;
            *(float4*)(cp + 0) = make_float4(acc[i][0] + rowadd[0], acc[i][1] + rowadd[1],
                                             acc[i][2] + rowadd[2], acc[i][3] + rowadd[3]);
            *(float4*)(cp + 4) = make_float4(acc[i][4] + rowadd[4], acc[i][5] + rowadd[5],
                                             acc[i][6] + rowadd[6], acc[i][7] + rowadd[7]);
        }
    }
}

// ---------------------------------------------------------------------------
// Aggregation (warp-per-node CSR gather), width 128:
//   D[i,:] = sn[i]*S[i,:] + sum_in w*S[src,:]  (+ CORR: c[i]*u2[:] + b[:])
// ---------------------------------------------------------------------------
template <int SSEL, int DSEL, int CORR>
__global__ __launch_bounds__(256)
void k_agg(const float* __restrict__ Sext,
           float* __restrict__ Dext,
           const float* __restrict__ b,
           int n) {
    int gw = (blockIdx.x * 256 + threadIdx.x) >> 5;
    if (gw >= n) return;
    int lane = threadIdx.x & 31;
    const float* S = pickc<SSEL>(Sext);
    float*       D = pick<DSEL>(Dext);

    int beg = g_off[gw];
    int end = g_off[gw + 1];
    float sn = g_sn[gw];
    float4 v = *(const float4*)(S + (size_t)gw * OUT_DIM + lane * 4);
    float4 acc = make_float4(sn * v.x, sn * v.y, sn * v.z, sn * v.w);

    for (int p = beg; p < end; p++) {
        int2 pr = g_adj[p];
        float w = __int_as_float(pr.y);
        float4 u = *(const float4*)(S + (size_t)pr.x * OUT_DIM + lane * 4);
        acc.x += w * u.x;
        acc.y += w * u.y;
        acc.z += w * u.z;
        acc.w += w * u.w;
    }

    if (CORR) {
        float ci = g_c[gw];
        int f = lane * 4;
        acc.x += ci * g_u2[f + 0] + b[f + 0];
        acc.y += ci * g_u2[f + 1] + b[f + 1];
        acc.z += ci * g_u2[f + 2] + b[f + 2];
        acc.w += ci * g_u2[f + 3] + b[f + 3];
    }
    *(float4*)(D + (size_t)gw * OUT_DIM + lane * 4) = acc;
}

// ---------------------------------------------------------------------------
static inline int ceil_div(int a, int b) { return (a + b - 1) / b; }

extern "C" void kernel_launch(void* const* d_in, const int* in_sizes, int n_in,
                              void* d_out, int out_size) {
    const float* features = (const float*)d_in[0];   // [N,1024]
    const void*  edge_idx = d_in[1];                 // [2,E] int32 or int64
    const float* W1       = (const float*)d_in[2];   // [512,1024]
    const float* b1       = (const float*)d_in[3];
    const float* W2       = (const float*)d_in[4];   // [128,512]
    const float* b2       = (const float*)d_in[5];
    const float* b3       = (const float*)d_in[6];
    const float* b4       = (const float*)d_in[7];
    const float* head1    = (const float*)d_in[8];   // [128,128]

    const int n = in_sizes[0] / IN_DIM;   // 20000
    const int e = in_sizes[1] / 2;        // 160000

    float* out = (float*)d_out;
    float* z_out  = out;
    float* h2_out = out + (size_t)n * OUT_DIM;
    float* h4_out = out + (size_t)n * OUT_DIM * 2;

    const int TPB = 256;
    dim3 blk(256);
    int aggb = ceil_div(n * 32, TPB);

    // ---- CSR + norm preprocessing ----
    k_probe_dtype<<<1, 32>>>((const int*)edge_idx);
    k_zero_cnt<<<ceil_div(n, TPB), TPB>>>(n);
    k_count<<<ceil_div(e, TPB), TPB>>>(edge_idx, e, n);
    k_dinv<<<ceil_div(n, TPB), TPB>>>(n);
    k_scan<<<1, 1024>>>(n);
    k_fill<<<ceil_div(e, TPB), TPB>>>(edge_idx, e, n);
    k_c<<<ceil_div(n, TPB), TPB>>>(n);

    // ---- weight precomputes ----
    {
        dim3 grid(IN_DIM / BN, 1);
        k_sgemm<0, 0, 0, 3, 0, 128><<<grid, blk>>>(OUT_DIM, IN_DIM, HID_DIM, W2, W1, nullptr, nullptr);
        k_u2<<<1, 128>>>(W2, b1);
        k_u4<<<ceil_div(IN_DIM, TPB), TPB>>>(W1, b3);
    }

    // ---- P = X @ W21^T [N,128] -> g_T (BM=64 for occupancy) ----
    {
        dim3 grid(1, ceil_div(n, 64));
        k_sgemm<1, 0, 3, 1, 0, 64><<<grid, blk>>>(n, OUT_DIM, IN_DIM, features, nullptr, nullptr, nullptr);
    }

    // ---- S1 = Ahat P -> g_H ;  h2 = Ahat S1 + c(x)u2 + b2 -> h2_out ----
    k_agg<1, 2, 0><<<aggb, blk>>>(nullptr, nullptr, nullptr, n);
    k_agg<2, 0, 1><<<aggb, blk>>>(nullptr, h2_out, b2, n);

    // ---- z = h2 @ head1 -> z_out ----
    {
        dim3 grid(1, ceil_div(n, 64));
        k_sgemm<0, 0, 0, 0, 0, 64><<<grid, blk>>>(n, OUT_DIM, OUT_DIM, h2_out, head1, z_out, nullptr);
    }

    // ---- S2 = Ahat z -> g_T ;  Q = Ahat S2 -> g_H ----
    k_agg<0, 1, 0><<<aggb, blk>>>(z_out, nullptr, nullptr, n);
    k_agg<1, 2, 0><<<aggb, blk>>>(nullptr, nullptr, nullptr, n);

    // ---- h4 = Q @ W21 + c(x)u4 + b4 -> h4_out ----
    {
        dim3 grid(IN_DIM / BN, ceil_div(n, 128));
        k_sgemm<0, 2, 3, 0, 1, 128><<<grid, blk>>>(n, IN_DIM, OUT_DIM, nullptr, nullptr, h4_out, b4);
    }

    (void)n_in; (void)out_size;
}